// round 6
// baseline (speedup 1.0000x reference)
#include <cuda_runtime.h>
#include <cuda_bf16.h>
#include <cstdint>

typedef unsigned long long u64;

constexpr int Bc = 2;
constexpr int Lc = 4096;
constexpr int DK = 128;
constexpr int DV = 128;
constexpr int C  = 64;
constexpr int NC = Lc / C;       // 64
constexpr int TC = Bc * NC;      // 128
constexpr float EPS = 1e-6f;

constexpr int PL = 66;           // l-contiguous row stride (transposed V in k3)
constexpr int PK = 130;          // k-contiguous row stride (Q, K, Spre in k3)
constexpr int PJ = 66;           // j-contiguous row stride (A in k3)

// Scratch: g_kv / g_kvpre stored [bc][v][k] (k contiguous)
__device__ float g_kv   [(size_t)TC * DK * DV];
__device__ float g_kvpre[(size_t)TC * DK * DV];
__device__ float g_ks   [(size_t)TC * DK];
__device__ float g_kspre[(size_t)TC * DK];

__device__ __forceinline__ float phi(float x) {
    return x > 0.f ? x + 1.f : __expf(x);
}

__device__ __forceinline__ void fma2(u64& d, u64 a, u64 b) {
    asm("fma.rn.f32x2 %0, %1, %2, %0;" : "+l"(d) : "l"(a), "l"(b));
}
__device__ __forceinline__ float2 up2(u64 v) {
    float2 f; asm("mov.b64 {%0, %1}, %2;" : "=f"(f.x), "=f"(f.y) : "l"(v)); return f;
}
__device__ __forceinline__ u64 lds64(const float* p) {
    return *reinterpret_cast<const u64*>(p);
}
__device__ __forceinline__ u64 dup2(float x) {
    u64 r; asm("mov.b64 %0, {%1, %1};" : "=l"(r) : "f"(x)); return r;
}

// ---------------------------------------------------------------------------
// Kernel 1: KV[k][v] = sum_l phiK[l][k] V[l][v]   (stored g_kv[bc][v][k])
// grid = 2*TC (v halves), 256 threads, 4 CTAs/SM.
// NO transposes: sK row-major [64][128], sV row-major [64][64].
// f32x2 packed along k (output dim): a = natural LDS.64 pair, b = dup scalar.
// ---------------------------------------------------------------------------
__global__ void __launch_bounds__(256, 4)
k_chunk_kv(const float* __restrict__ K, const float* __restrict__ V) {
    __shared__ float sK[C * DK];    // 32 KB, row-major (k contig)
    __shared__ float sV[C * 64];    // 16 KB, row-major (v contig, half)

    const int bc = blockIdx.x >> 1;
    const int vh = (blockIdx.x & 1) * 64;
    const int b  = bc / NC;
    const int c  = bc % NC;
    const int l0 = c * C;
    const int tid = threadIdx.x;

    // stage K (full, with phi): coalesced float4 -> conflict-free float4 STS
    for (int e = tid; e < 2048; e += 256) {
        const int l = e >> 5, k4 = (e & 31) * 4;
        float4 x = *(const float4*)&K[((size_t)(b * Lc + l0 + l)) * DK + k4];
        *(float4*)&sK[l * DK + k4] = make_float4(phi(x.x), phi(x.y), phi(x.z), phi(x.w));
    }
    // stage V half: coalesced float4 -> conflict-free float4 STS
    for (int e = tid; e < 1024; e += 256) {
        const int l = e >> 4, v4 = (e & 15) * 4;
        float4 x = *(const float4*)&V[((size_t)(b * Lc + l0 + l)) * DV + vh + v4];
        *(float4*)&sV[l * 64 + v4] = x;
    }
    __syncthreads();

    const int w = tid >> 5, tx = tid & 31;
    const int half = tx >> 4, txl = tx & 15;
    const int k0 = w * 16 + half * 8;     // 8 k per thread (4 pairs)
    const int v0 = txl * 4;               // 4 consecutive v per thread

    u64 acc[4][4];                        // [k-pair r][v s]
#pragma unroll
    for (int r = 0; r < 4; r++)
#pragma unroll
        for (int s = 0; s < 4; s++) acc[r][s] = 0ull;

#pragma unroll 8
    for (int l = 0; l < C; l++) {
        const float* kr = &sK[l * DK + k0];
        u64 a0 = lds64(kr), a1 = lds64(kr + 2), a2 = lds64(kr + 4), a3 = lds64(kr + 6);
        float4 bv = *(const float4*)&sV[l * 64 + v0];
        u64 b0 = dup2(bv.x), b1 = dup2(bv.y), b2 = dup2(bv.z), b3 = dup2(bv.w);
        fma2(acc[0][0], a0, b0); fma2(acc[0][1], a0, b1);
        fma2(acc[0][2], a0, b2); fma2(acc[0][3], a0, b3);
        fma2(acc[1][0], a1, b0); fma2(acc[1][1], a1, b1);
        fma2(acc[1][2], a1, b2); fma2(acc[1][3], a1, b3);
        fma2(acc[2][0], a2, b0); fma2(acc[2][1], a2, b1);
        fma2(acc[2][2], a2, b2); fma2(acc[2][3], a2, b3);
        fma2(acc[3][0], a3, b0); fma2(acc[3][1], a3, b1);
        fma2(acc[3][2], a3, b2); fma2(acc[3][3], a3, b3);
    }

    // store g_kv[bc][v][k0..k0+7]: two float4 per v (k0 multiple of 8 -> aligned)
    float* kvout = g_kv + (size_t)bc * DK * DV;
#pragma unroll
    for (int s = 0; s < 4; s++) {
        const int v = vh + v0 + s;
        float2 p0 = up2(acc[0][s]), p1 = up2(acc[1][s]);
        float2 p2 = up2(acc[2][s]), p3 = up2(acc[3][s]);
        *(float4*)&kvout[(size_t)v * DK + k0]     = make_float4(p0.x, p0.y, p1.x, p1.y);
        *(float4*)&kvout[(size_t)v * DK + k0 + 4] = make_float4(p2.x, p2.y, p3.x, p3.y);
    }

    // per-chunk phiK column sums (v-half 0 only): stride-128 reads, conflict-free
    if (vh == 0 && tid < DK) {
        float s = 0.f;
#pragma unroll 8
        for (int l = 0; l < C; l++) s += sK[l * DK + tid];
        g_ks[(size_t)bc * DK + tid] = s;
    }
}

// ---------------------------------------------------------------------------
// Kernel 2: warp-parallel exclusive scan over chunks
// ---------------------------------------------------------------------------
__device__ __forceinline__ float warp_excl_scan(float x, int lane) {
#pragma unroll
    for (int d = 1; d < 32; d <<= 1) {
        float t = __shfl_up_sync(0xffffffffu, x, d);
        if (lane >= d) x += t;
    }
    float e = __shfl_up_sync(0xffffffffu, x, 1);
    return lane == 0 ? 0.f : e;
}

__global__ void __launch_bounds__(512, 2)
k_scan(void) {
    const int gw = blockIdx.x * 16 + (threadIdx.x >> 5);
    const int lane = threadIdx.x & 31;
    if (gw < 8192) {
        const int b   = gw >> 12;
        const int rem = gw & 4095;
        const int v   = rem >> 5;
        const int k4  = (rem & 31) * 4;
        const size_t cstr = (size_t)DK * DV;
        const size_t base = (size_t)(b * NC) * cstr + (size_t)v * DK + k4;

        float4 carry = make_float4(0.f, 0.f, 0.f, 0.f);
#pragma unroll
        for (int pass = 0; pass < 2; pass++) {
            const size_t idx = base + (size_t)(pass * 32 + lane) * cstr;
            float4 x = *(const float4*)(g_kv + idx);
            float4 ex;
            ex.x = warp_excl_scan(x.x, lane) + carry.x;
            ex.y = warp_excl_scan(x.y, lane) + carry.y;
            ex.z = warp_excl_scan(x.z, lane) + carry.z;
            ex.w = warp_excl_scan(x.w, lane) + carry.w;
            *(float4*)(g_kvpre + idx) = ex;
            carry.x = __shfl_sync(0xffffffffu, ex.x + x.x, 31);
            carry.y = __shfl_sync(0xffffffffu, ex.y + x.y, 31);
            carry.z = __shfl_sync(0xffffffffu, ex.z + x.z, 31);
            carry.w = __shfl_sync(0xffffffffu, ex.w + x.w, 31);
        }
    } else if (gw < 8192 + 64) {
        const int t  = gw - 8192;
        const int b  = t >> 5;
        const int k4 = (t & 31) * 4;
        const size_t base = (size_t)(b * NC) * DK + k4;
        float4 carry = make_float4(0.f, 0.f, 0.f, 0.f);
#pragma unroll
        for (int pass = 0; pass < 2; pass++) {
            const size_t idx = base + (size_t)(pass * 32 + lane) * DK;
            float4 x = *(const float4*)(g_ks + idx);
            float4 ex;
            ex.x = warp_excl_scan(x.x, lane) + carry.x;
            ex.y = warp_excl_scan(x.y, lane) + carry.y;
            ex.z = warp_excl_scan(x.z, lane) + carry.z;
            ex.w = warp_excl_scan(x.w, lane) + carry.w;
            *(float4*)(g_kspre + idx) = ex;
            carry.x = __shfl_sync(0xffffffffu, ex.x + x.x, 31);
            carry.y = __shfl_sync(0xffffffffu, ex.y + x.y, 31);
            carry.z = __shfl_sync(0xffffffffu, ex.z + x.z, 31);
            carry.w = __shfl_sync(0xffffffffu, ex.w + x.w, 31);
        }
    }
}

// ---------------------------------------------------------------------------
// Kernel 3: A = mask(phiQ phiK^T); out = (A V + phiQ Spre) / Z
// ---------------------------------------------------------------------------
__global__ void __launch_bounds__(512, 1)
k_output(const float* __restrict__ Q, const float* __restrict__ K,
         const float* __restrict__ V, float* __restrict__ out) {
    extern __shared__ float sm[];
    float* sQ  = sm;                        // [64][PK] phiQ row-major (k contig)
    float* sK  = sQ  + C * PK;              // [64][PK] phiK row-major
    float* sA  = sK  + C * PK;              // [64][PJ] A row-major (j contig)
    float* sVt = sA  + C * PJ;              // [128][PL] V transposed (l contig)
    float* sSt = sVt + DV * PL;             // [128][PK] Spre [v][k] (k contig)
    float* sKs = sSt + DV * PK;             // [128]
    float* sZ  = sKs + DK;                  // [64]

    const int bc = blockIdx.x;
    const int b  = bc / NC;
    const int c  = bc % NC;
    const int l0 = c * C;
    const int tid = threadIdx.x;

    // Q, K row-major with phi: lane -> k strided by 32, conflict-free STS
    for (int e = tid; e < 2048; e += 512) {
        const int l = e >> 5, kb = e & 31;
        const size_t g = ((size_t)(b * Lc + l0 + l)) * DK + kb;
        float* dq = &sQ[l * PK + kb];
        float* dk = &sK[l * PK + kb];
#pragma unroll
        for (int j = 0; j < 4; j++) {
            dq[j * 32] = phi(Q[g + j * 32]);
            dk[j * 32] = phi(K[g + j * 32]);
        }
    }
    // V transpose: 2-way STS conflicts only
    for (int e = tid; e < 2048; e += 512) {
        const int l = e >> 5, vb = e & 31;
        const float* src = &V[((size_t)(b * Lc + l0 + l)) * DV + vb];
        float* dst = &sVt[vb * PL + l];
#pragma unroll
        for (int j = 0; j < 4; j++)
            dst[j * 32 * PL] = src[j * 32];
    }
    // stage Spre [v][k]: coalesced loads, conflict-free STS
    {
        const float* Sp = g_kvpre + (size_t)bc * DK * DV;
        for (int e = tid; e < 4096; e += 512) {
            const int v = e >> 5, kb = e & 31;
            const float* src = &Sp[(size_t)v * DK + kb];
            float* dst = &sSt[v * PK + kb];
#pragma unroll
            for (int j = 0; j < 4; j++)
                dst[j * 32] = src[j * 32];
        }
    }
    if (tid < DK) sKs[tid] = g_kspre[(size_t)bc * DK + tid];
    if (tid < C)  sZ[tid] = 0.f;
    __syncthreads();

    const int w = tid >> 5, tx = tid & 31;
    const int half = tx >> 4, txl = tx & 15;

    // ---- phase 1: A (pair over k). thread: 2 i x 4 j ----
    {
        const int i0 = w * 4 + half * 2;
        u64 aA[2][4];
#pragma unroll
        for (int r = 0; r < 2; r++)
#pragma unroll
            for (int s = 0; s < 4; s++) aA[r][s] = 0ull;

#pragma unroll
        for (int kp = 0; kp < DK / 2; kp++) {
            u64 a0 = lds64(&sQ[(i0    ) * PK + 2 * kp]);
            u64 a1 = lds64(&sQ[(i0 + 1) * PK + 2 * kp]);
            u64 bb[4];
#pragma unroll
            for (int s = 0; s < 4; s++) bb[s] = lds64(&sK[(txl + 16 * s) * PK + 2 * kp]);
#pragma unroll
            for (int s = 0; s < 4; s++) { fma2(aA[0][s], a0, bb[s]); fma2(aA[1][s], a1, bb[s]); }
        }
#pragma unroll
        for (int r = 0; r < 2; r++)
#pragma unroll
            for (int s = 0; s < 4; s++) {
                const int i = i0 + r, j = txl + 16 * s;
                float2 v = up2(aA[r][s]);
                sA[i * PJ + j] = (i >= j) ? (v.x + v.y) : 0.f;
            }
    }
    __syncthreads();

    // ---- Z: rowsum(A) + phiQ . Kspre (8 partials per row) ----
    {
        const int iz = tid & 63, p = tid >> 6;
        float zp = 0.f;
#pragma unroll
        for (int j = p * 8; j < p * 8 + 8; j++) zp += sA[iz * PJ + j];
#pragma unroll
        for (int k = p * 16; k < p * 16 + 16; k++) zp += sQ[iz * PK + k] * sKs[k];
        atomicAdd(&sZ[iz], zp);
    }

    // ---- phase 2: out = A V + phiQ Spre (pair over j / k). thread: 4 i x 4 v ----
    const int i0 = (w & 7) * 8 + half * 4;
    const int vg = (w >> 3) * 64;
    u64 acc[4][4];
#pragma unroll
    for (int r = 0; r < 4; r++)
#pragma unroll
        for (int s = 0; s < 4; s++) acc[r][s] = 0ull;

#pragma unroll
    for (int jp = 0; jp < C / 2; jp++) {          // intra-chunk
        u64 a[4], bb[4];
#pragma unroll
        for (int r = 0; r < 4; r++) a[r] = lds64(&sA[(i0 + r) * PJ + 2 * jp]);
#pragma unroll
        for (int s = 0; s < 4; s++) bb[s] = lds64(&sVt[(vg + txl + 16 * s) * PL + 2 * jp]);
#pragma unroll
        for (int r = 0; r < 4; r++)
#pragma unroll
            for (int s = 0; s < 4; s++) fma2(acc[r][s], a[r], bb[s]);
    }
#pragma unroll
    for (int kp = 0; kp < DK / 2; kp++) {         // inter-chunk
        u64 a[4], bb[4];
#pragma unroll
        for (int r = 0; r < 4; r++) a[r] = lds64(&sQ[(i0 + r) * PK + 2 * kp]);
#pragma unroll
        for (int s = 0; s < 4; s++) bb[s] = lds64(&sSt[(vg + txl + 16 * s) * PK + 2 * kp]);
#pragma unroll
        for (int r = 0; r < 4; r++)
#pragma unroll
            for (int s = 0; s < 4; s++) fma2(acc[r][s], a[r], bb[s]);
    }

    __syncthreads();   // sZ complete

#pragma unroll
    for (int r = 0; r < 4; r++) {
        const int i = i0 + r;
        const float invz = 1.f / (sZ[i] + EPS);
        const size_t g = ((size_t)(b * Lc + l0 + i)) * DV;
#pragma unroll
        for (int s = 0; s < 4; s++) {
            float2 v = up2(acc[r][s]);
            out[g + vg + txl + 16 * s] = (v.x + v.y) * invz;
        }
    }
}

// ---------------------------------------------------------------------------
extern "C" void kernel_launch(void* const* d_in, const int* in_sizes, int n_in,
                              void* d_out, int out_size) {
    const float* Q = (const float*)d_in[0];
    const float* K = (const float*)d_in[1];
    const float* V = (const float*)d_in[2];
    float* out = (float*)d_out;

    const int smem3 = (2 * C * PK + C * PJ + DV * PL + DV * PK + DK + C)
                      * (int)sizeof(float);                                      // ~184.6 KB

    cudaFuncSetAttribute(k_output, cudaFuncAttributeMaxDynamicSharedMemorySize, smem3);

    k_chunk_kv<<<2 * TC, 256>>>(K, V);
    k_scan<<<516, 512>>>();
    k_output<<<TC, 512, smem3>>>(Q, K, V, out);
}